// round 16
// baseline (speedup 1.0000x reference)
#include <cuda_runtime.h>
#include <cstdint>

#define NB 1024
#define NC 500000
#define ND 64
#define NK 50
#define NR 296                 // sweep CTAs = two per SM
#define RC 1728                // columns per range = 27 tiles x 64
#define TPT 27
#define TILE 64
#define NPAD (NR * RC)         // 511488 padded rows
#define CAP 6144               // per-query candidate capacity
#define QS 25.0f
#define NSMP 2048              // tau sample size
#define SSTRIDE 244            // 2047*244 = 499468 < NC
#define NTAU 6                 // ~1460 qualifiers/query

typedef unsigned int u32;

// ------------------------- device-global scratch ---------------------------
__device__ __align__(16) unsigned char g_t8[(size_t)NPAD * 64];  // packed int8 table
__device__ __align__(8) int2 g_meta[NPAD];                       // {nt, srt} per row
__device__ __align__(16) unsigned char g_q8[NB * 64];            // packed int8 queries
__device__ int g_srq[NB];                                        // ceil sqrt of q rest-norm
__device__ int g_tau[NB];                                        // per-query threshold
__device__ u32 g_cnt[NB];                                        // per-query counts
__device__ int g_cand[(size_t)NB * CAP];                         // candidate rows

// ------------------------------ helpers ------------------------------------
__device__ __forceinline__ u32 smem_u32(const void* p) {
    u32 a;
    asm("{ .reg .u64 t; cvta.to.shared.u64 t, %1; cvt.u32.u64 %0, t; }" : "=r"(a) : "l"(p));
    return a;
}
__device__ __forceinline__ void cpa16(u32 s, const void* g) {
    asm volatile("cp.async.cg.shared.global [%0], [%1], 16;" :: "r"(s), "l"(g));
}
__device__ __forceinline__ void cpa_commit() { asm volatile("cp.async.commit_group;" ::: "memory"); }
__device__ __forceinline__ void cpa_wait2()  { asm volatile("cp.async.wait_group 2;" ::: "memory"); }

__device__ __forceinline__ int isqrt_ceil(int x) {
    int s = (int)sqrtf((float)x);
    while (s * s < x) s++;
    return s;
}
__device__ __forceinline__ void load16(const unsigned char* src, u32* w) {
    const uint4* p = (const uint4*)src;
#pragma unroll
    for (int i = 0; i < 4; i++) {
        uint4 x = p[i];
        w[4 * i] = x.x; w[4 * i + 1] = x.y; w[4 * i + 2] = x.z; w[4 * i + 3] = x.w;
    }
}

// ---------------------------------------------------------------------------
// prep_t: warp-cooperative, fully coalesced. 16 lanes per row, 2 rows/warp.
// Emits packed int8 words, full norm nt, and srt = ceil(sqrt(rest-norm)).
// ---------------------------------------------------------------------------
__global__ void __launch_bounds__(256)
prep_t(const float* __restrict__ tkeys) {
    const int tid = threadIdx.x;
    const int warp = tid >> 5, lane = tid & 31;
    const int grp = lane >> 4, sub = lane & 15;
    const int row = blockIdx.x * 16 + warp * 2 + grp;   // grid covers NPAD exactly

    u32 w = 0;
    int nf = 0;
    if (row < NC) {
        float4 v = __ldg(&((const float4*)tkeys)[(size_t)row * 16 + sub]);
        int r0 = max(-127, min(127, __float2int_rn(v.x * QS)));
        int r1 = max(-127, min(127, __float2int_rn(v.y * QS)));
        int r2 = max(-127, min(127, __float2int_rn(v.z * QS)));
        int r3 = max(-127, min(127, __float2int_rn(v.w * QS)));
        nf = r0 * r0 + r1 * r1 + r2 * r2 + r3 * r3;
        w = (u32)(r0 & 255) | ((u32)(r1 & 255) << 8) |
            ((u32)(r2 & 255) << 16) | ((u32)(r3 & 255) << 24);
    }
    // reduce within 16-lane group
    int nfull = nf;
    int nrest = (sub >= 8) ? nf : 0;
#pragma unroll
    for (int o = 1; o < 16; o <<= 1) {
        nfull += __shfl_xor_sync(0xffffffffu, nfull, o);
        nrest += __shfl_xor_sync(0xffffffffu, nrest, o);
    }
    // write word (coalesced 64B/row)
    *(u32*)(g_t8 + (size_t)row * 64 + sub * 4) = w;
    if (sub == 0) {
        int2 m;
        if (row < NC) { m.x = nfull; m.y = isqrt_ceil(nrest); }
        else          { m.x = 1 << 29; m.y = 0; }
        g_meta[row] = m;
    }
}

// prep_q: quantize queries + srq
__global__ void __launch_bounds__(256)
prep_q(const float* __restrict__ keys) {
    const int p = blockIdx.x * 256 + threadIdx.x;
    if (p >= NB) return;
    const float4* sp = (const float4*)(keys + (size_t)p * ND);
    u32 w[16];
    int nrest = 0;
#pragma unroll
    for (int j = 0; j < 16; j++) {
        float4 x = __ldg(sp + j);
        float v[4] = {x.x, x.y, x.z, x.w};
        u32 pk = 0;
        int ns = 0;
#pragma unroll
        for (int e = 0; e < 4; e++) {
            int r = max(-127, min(127, __float2int_rn(v[e] * QS)));
            ns += r * r;
            pk |= ((u32)(r & 255)) << (8 * e);
        }
        w[j] = pk;
        if (j >= 8) nrest += ns;
    }
    uint4* dst = (uint4*)(g_q8 + (size_t)p * 64);
    dst[0] = make_uint4(w[0], w[1], w[2], w[3]);
    dst[1] = make_uint4(w[4], w[5], w[6], w[7]);
    dst[2] = make_uint4(w[8], w[9], w[10], w[11]);
    dst[3] = make_uint4(w[12], w[13], w[14], w[15]);
    g_srq[p] = isqrt_ceil(nrest);
}

// ---------------------------------------------------------------------------
// tau_kernel: per-query threshold from 2048-row sample; resets counter
// ---------------------------------------------------------------------------
__global__ void __launch_bounds__(256)
tau_kernel() {
    __shared__ int s_s[NSMP];
    __shared__ int rv[8], rp[8];
    __shared__ int s_tau;

    const int q = blockIdx.x, tid = threadIdx.x;
    const int w = tid >> 5, lane = tid & 31;

    u32 qw[16];
    load16(g_q8 + (size_t)q * 64, qw);

#pragma unroll
    for (int i = 0; i < NSMP / 256; i++) {
        const int j = tid + i * 256;
        const int r = j * SSTRIDE;
        u32 tw[16];
        load16(g_t8 + (size_t)r * 64, tw);
        int d = 0;
#pragma unroll
        for (int k = 0; k < 16; k++) d = __dp4a((int)tw[k], (int)qw[k], d);
        s_s[j] = g_meta[r].x - 2 * d;
    }
    __syncthreads();

    for (int k = 0; k < NTAU; k++) {
        int v = 0x7FFFFFFF, p = 0;
        for (int i = tid; i < NSMP; i += 256)
            if (s_s[i] < v) { v = s_s[i]; p = i; }
#pragma unroll
        for (int o = 16; o > 0; o >>= 1) {
            int ov = __shfl_down_sync(0xffffffffu, v, o);
            int op = __shfl_down_sync(0xffffffffu, p, o);
            if (ov < v) { v = ov; p = op; }
        }
        if (lane == 0) { rv[w] = v; rp[w] = p; }
        __syncthreads();
        if (tid == 0) {
            int bv = rv[0], bp = rp[0];
#pragma unroll
            for (int x = 1; x < 8; x++)
                if (rv[x] < bv) { bv = rv[x]; bp = rp[x]; }
            s_s[bp] = 0x7FFFFFFF;
            if (k == NTAU - 1) s_tau = bv;
        }
        __syncthreads();
    }
    if (tid == 0) { g_tau[q] = s_tau; g_cnt[q] = 0u; }
}

// ---------------------------------------------------------------------------
// sweep: Cauchy-Schwarz screened dp4a sweep. Head = words 0-7 always;
// rest computed only when the integer lower bound can beat tau (rigorous).
// 296 CTAs x 512 threads (2/SM), 2 queries/thread.
// ---------------------------------------------------------------------------
__global__ void __launch_bounds__(512, 2)
sweep_kernel() {
    __shared__ __align__(16) u32 s_t[3][TILE * 16];   // 3 x 4KB column data
    __shared__ __align__(16) int2 s_m[3][TILE];       // 3 x 512B {nt, srt}

    const int tid = threadIdx.x;
    const int range = blockIdx.x;
    const int q0 = tid * 2, q1 = q0 + 1;
    const u32 sbt = smem_u32(&s_t[0][0]);
    const u32 sbm = smem_u32(&s_m[0][0]);

    u32 q0w[16], q1w[16];
    load16(g_q8 + (size_t)q0 * 64, q0w);
    load16(g_q8 + (size_t)q1 * 64, q1w);
    const int t0 = g_tau[q0] + 1;     // qualify: s < t0
    const int t1 = g_tau[q1] + 1;
    const int srq02 = 2 * g_srq[q0];
    const int srq12 = 2 * g_srq[q1];

    const size_t rbase = (size_t)range * RC;
    auto prefetch = [&](int t, int st) {
        const unsigned char* src = g_t8 + (rbase + (size_t)t * TILE) * 64;
        if (tid < 256) cpa16(sbt + st * 4096 + tid * 16, src + tid * 16);
        else if (tid < 288)
            cpa16(sbm + st * 512 + (tid - 256) * 16,
                  (const unsigned char*)(g_meta + rbase + (size_t)t * TILE) + (tid - 256) * 16);
        cpa_commit();
    };

    prefetch(0, 0); prefetch(1, 1); prefetch(2, 2);

    for (int t = 0; t < TPT; t++) {
        const int st = t % 3;
        cpa_wait2();
        __syncthreads();

        const u32* tp = s_t[st];
        const int2* mp = s_m[st];
        const int pbase = range * RC + t * TILE;

#pragma unroll 4
        for (int c = 0; c < TILE; c++) {
            const uint4* col = (const uint4*)(tp + c * 16);
            const uint4 x0 = col[0];
            const uint4 x1 = col[1];
            const int2 mt = mp[c];

            // head dot (words 0-7), 2 chains per query
            int a0 = 0, b0 = 0, a1 = 0, b1 = 0;
            a0 = __dp4a((int)x0.x, (int)q0w[0], a0);
            a1 = __dp4a((int)x0.x, (int)q1w[0], a1);
            b0 = __dp4a((int)x1.x, (int)q0w[4], b0);
            b1 = __dp4a((int)x1.x, (int)q1w[4], b1);
            a0 = __dp4a((int)x0.y, (int)q0w[1], a0);
            a1 = __dp4a((int)x0.y, (int)q1w[1], a1);
            b0 = __dp4a((int)x1.y, (int)q0w[5], b0);
            b1 = __dp4a((int)x1.y, (int)q1w[5], b1);
            a0 = __dp4a((int)x0.z, (int)q0w[2], a0);
            a1 = __dp4a((int)x0.z, (int)q1w[2], a1);
            b0 = __dp4a((int)x1.z, (int)q0w[6], b0);
            b1 = __dp4a((int)x1.z, (int)q1w[6], b1);
            a0 = __dp4a((int)x0.w, (int)q0w[3], a0);
            a1 = __dp4a((int)x0.w, (int)q1w[3], a1);
            b0 = __dp4a((int)x1.w, (int)q0w[7], b0);
            b1 = __dp4a((int)x1.w, (int)q1w[7], b1);
            const int dh0 = a0 + b0;
            const int dh1 = a1 + b1;

            // rigorous lower bounds: s >= nt - 2*dh - 2*srt*srq
            const int v0 = mt.x - t0 - 2 * dh0 - mt.y * srq02;
            const int v1 = mt.x - t1 - 2 * dh1 - mt.y * srq12;

            if (min(v0, v1) < 0) {              // rare tail: exact rest dot
                const uint4 y0 = col[2];
                const uint4 y1 = col[3];
                int c0 = 0, d0 = 0, c1 = 0, d1 = 0;
                c0 = __dp4a((int)y0.x, (int)q0w[8],  c0);
                c1 = __dp4a((int)y0.x, (int)q1w[8],  c1);
                d0 = __dp4a((int)y1.x, (int)q0w[12], d0);
                d1 = __dp4a((int)y1.x, (int)q1w[12], d1);
                c0 = __dp4a((int)y0.y, (int)q0w[9],  c0);
                c1 = __dp4a((int)y0.y, (int)q1w[9],  c1);
                d0 = __dp4a((int)y1.y, (int)q0w[13], d0);
                d1 = __dp4a((int)y1.y, (int)q1w[13], d1);
                c0 = __dp4a((int)y0.z, (int)q0w[10], c0);
                c1 = __dp4a((int)y0.z, (int)q1w[10], c1);
                d0 = __dp4a((int)y1.z, (int)q0w[14], d0);
                d1 = __dp4a((int)y1.z, (int)q1w[14], d1);
                c0 = __dp4a((int)y0.w, (int)q0w[11], c0);
                c1 = __dp4a((int)y0.w, (int)q1w[11], c1);
                d0 = __dp4a((int)y1.w, (int)q0w[15], d0);
                d1 = __dp4a((int)y1.w, (int)q1w[15], d1);
                const int s0 = mt.x - 2 * (dh0 + c0 + d0);
                const int s1 = mt.x - 2 * (dh1 + c1 + d1);
                const int p0 = pbase + c;
                if (s0 < t0) {
                    u32 i = atomicAdd(&g_cnt[q0], 1u);
                    if (i < CAP) g_cand[(size_t)q0 * CAP + i] = p0;
                }
                if (s1 < t1) {
                    u32 i = atomicAdd(&g_cnt[q1], 1u);
                    if (i < CAP) g_cand[(size_t)q1 * CAP + i] = p0;
                }
            }
        }

        __syncthreads();
        if (t + 3 < TPT) prefetch(t + 3, st);
        else cpa_commit();
    }
}

// ---------------------------------------------------------------------------
// merge: exact fp32 rerank (512 thr, ILP-2) -> exact top-50 -> weighted avg
// ---------------------------------------------------------------------------
__global__ void __launch_bounds__(512)
merge_kernel(const float* __restrict__ keys, const float* __restrict__ tkeys,
             const float* __restrict__ tvals, float* __restrict__ out) {
    __shared__ float sd[CAP];
    __shared__ __align__(16) float qs[ND];
    __shared__ float frv[16]; __shared__ int frp[16];
    __shared__ float selv[NK]; __shared__ int sel2[NK];
    __shared__ float ws[NK], wv[NK];

    const int q = blockIdx.x, tid = threadIdx.x;
    const int w = tid >> 5, lane = tid & 31;
    const float INF = __int_as_float(0x7f800000);
    const int n = min((int)g_cnt[q], CAP);
    const int* cand = g_cand + (size_t)q * CAP;

    if (tid < ND) qs[tid] = keys[(size_t)q * ND + tid];
    __syncthreads();

    // exact squared distances: warp per candidate, 2 rows in flight, 16 warps
    {
        const float2 qv = ((const float2*)qs)[lane];
        for (int cb = w; cb < n; cb += 32) {
            const int cb2 = cb + 16;
            const bool has2 = cb2 < n;
            const int ra = cand[cb];
            const int rb = cand[has2 ? cb2 : cb];
            const float2 ta = ((const float2*)(tkeys + (size_t)ra * ND))[lane];
            const float2 tb = ((const float2*)(tkeys + (size_t)rb * ND))[lane];
            float a0 = qv.x - ta.x, a1 = qv.y - ta.y;
            float b0 = qv.x - tb.x, b1 = qv.y - tb.y;
            float sa = fmaf(a0, a0, a1 * a1);
            float sc = fmaf(b0, b0, b1 * b1);
#pragma unroll
            for (int o = 16; o > 0; o >>= 1) {
                sa += __shfl_xor_sync(0xffffffffu, sa, o);
                sc += __shfl_xor_sync(0xffffffffu, sc, o);
            }
            if (lane == 0) {
                sd[cb] = sa;
                if (has2) sd[cb2] = sc;
            }
        }
    }
    __syncthreads();

    // exact top-50 by iterative argmin over n candidates
    for (int k = 0; k < NK; k++) {
        float v = INF; int p = 0;
        for (int i = tid; i < n; i += 512)
            if (sd[i] < v) { v = sd[i]; p = i; }
#pragma unroll
        for (int o = 16; o > 0; o >>= 1) {
            float ov = __shfl_down_sync(0xffffffffu, v, o);
            int   op = __shfl_down_sync(0xffffffffu, p, o);
            if (ov < v) { v = ov; p = op; }
        }
        if (lane == 0) { frv[w] = v; frp[w] = p; }
        __syncthreads();
        if (tid == 0) {
            float bv = frv[0]; int bp = frp[0];
#pragma unroll
            for (int x = 1; x < 16; x++)
                if (frv[x] < bv) { bv = frv[x]; bp = frp[x]; }
            selv[k] = bv; sel2[k] = bp;
            sd[bp] = INF;
        }
        __syncthreads();
    }

    if (tid < NK) {
        float dv = selv[tid];
        float wgt = (dv < INF) ? 1.0f / (dv + 1e-3f) : 0.0f;
        ws[tid] = wgt;
        wv[tid] = wgt * tvals[cand[sel2[tid]]];
    }
    __syncthreads();
    if (tid == 0) {
        float sw = 0.f, sv = 0.f;
#pragma unroll
        for (int k = 0; k < NK; k++) { sw += ws[k]; sv += wv[k]; }
        out[q] = sv / sw;
    }
}

// ---------------------------------------------------------------------------
extern "C" void kernel_launch(void* const* d_in, const int* in_sizes, int n_in,
                              void* d_out, int out_size) {
    const float* keys  = (const float*)d_in[0];   // [1024, 64]
    const float* tkeys = (const float*)d_in[1];   // [500000, 64]
    const float* tvals = (const float*)d_in[2];   // [500000]
    float* out = (float*)d_out;                   // [1024]

    prep_t<<<NPAD / 16, 256>>>(tkeys);            // 31968 blocks, exact cover
    prep_q<<<4, 256>>>(keys);
    tau_kernel<<<NB, 256>>>();                    // thresholds + counter reset
    sweep_kernel<<<NR, 512>>>();
    merge_kernel<<<NB, 512>>>(keys, tkeys, tvals, out);
}

// round 17
// speedup vs baseline: 1.3700x; 1.3700x over previous
#include <cuda_runtime.h>
#include <cstdint>

#define NB 1024
#define NC 500000
#define ND 64
#define NK 50
#define NR 296                 // sweep CTAs = two per SM
#define RC 1728                // columns per range = 27 tiles x 64
#define TPT 27
#define TILE 64
#define NPAD (NR * RC)         // 511488 padded rows
#define CAP 6144               // per-query candidate capacity
#define QS 25.0f
#define NSMP 2048              // tau sample size
#define SSTRIDE 244            // 2047*244 = 499468 < NC
#define NTAU 6                 // ~1460 qualifiers/query
#define MQ 80                  // quant-top target for exact rerank
#define MCAP 128               // rerank capacity

typedef unsigned int u32;

// ------------------------- device-global scratch ---------------------------
__device__ __align__(16) unsigned char g_t8[(size_t)NPAD * 64];  // packed int8 table
__device__ int g_nint[NPAD];                                     // int norms (pad huge)
__device__ __align__(16) unsigned char g_q8[NB * 64];            // packed int8 queries
__device__ int g_tau[NB];                                        // per-query threshold
__device__ u32 g_cnt[NB];                                        // per-query counts
__device__ int g_cand[(size_t)NB * CAP];                         // candidate rows
__device__ int g_csc[(size_t)NB * CAP];                          // candidate quant scores

// ------------------------------ helpers ------------------------------------
__device__ __forceinline__ u32 smem_u32(const void* p) {
    u32 a;
    asm("{ .reg .u64 t; cvta.to.shared.u64 t, %1; cvt.u32.u64 %0, t; }" : "=r"(a) : "l"(p));
    return a;
}
__device__ __forceinline__ void cpa16(u32 s, const void* g) {
    asm volatile("cp.async.cg.shared.global [%0], [%1], 16;" :: "r"(s), "l"(g));
}
__device__ __forceinline__ void cpa_commit() { asm volatile("cp.async.commit_group;" ::: "memory"); }
__device__ __forceinline__ void cpa_wait2()  { asm volatile("cp.async.wait_group 2;" ::: "memory"); }

__device__ __forceinline__ void load16(const unsigned char* src, u32* w) {
    const uint4* p = (const uint4*)src;
#pragma unroll
    for (int i = 0; i < 4; i++) {
        uint4 x = p[i];
        w[4 * i] = x.x; w[4 * i + 1] = x.y; w[4 * i + 2] = x.z; w[4 * i + 3] = x.w;
    }
}

// ---------------------------------------------------------------------------
// prep_t: warp-cooperative, fully coalesced. 16 lanes per row, 2 rows/warp.
// ---------------------------------------------------------------------------
__global__ void __launch_bounds__(256)
prep_t(const float* __restrict__ tkeys) {
    const int tid = threadIdx.x;
    const int warp = tid >> 5, lane = tid & 31;
    const int grp = lane >> 4, sub = lane & 15;
    const int row = blockIdx.x * 16 + warp * 2 + grp;   // grid covers NPAD exactly

    u32 w = 0;
    int nf = 0;
    if (row < NC) {
        float4 v = __ldg(&((const float4*)tkeys)[(size_t)row * 16 + sub]);
        int r0 = max(-127, min(127, __float2int_rn(v.x * QS)));
        int r1 = max(-127, min(127, __float2int_rn(v.y * QS)));
        int r2 = max(-127, min(127, __float2int_rn(v.z * QS)));
        int r3 = max(-127, min(127, __float2int_rn(v.w * QS)));
        nf = r0 * r0 + r1 * r1 + r2 * r2 + r3 * r3;
        w = (u32)(r0 & 255) | ((u32)(r1 & 255) << 8) |
            ((u32)(r2 & 255) << 16) | ((u32)(r3 & 255) << 24);
    }
    int nfull = nf;
#pragma unroll
    for (int o = 1; o < 16; o <<= 1)
        nfull += __shfl_xor_sync(0xffffffffu, nfull, o);
    *(u32*)(g_t8 + (size_t)row * 64 + sub * 4) = w;
    if (sub == 0) g_nint[row] = (row < NC) ? nfull : (1 << 29);
}

// prep_q: quantize queries
__global__ void __launch_bounds__(256)
prep_q(const float* __restrict__ keys) {
    const int p = blockIdx.x * 256 + threadIdx.x;
    if (p >= NB) return;
    const float4* sp = (const float4*)(keys + (size_t)p * ND);
    u32 w[16];
#pragma unroll
    for (int j = 0; j < 16; j++) {
        float4 x = __ldg(sp + j);
        float v[4] = {x.x, x.y, x.z, x.w};
        u32 pk = 0;
#pragma unroll
        for (int e = 0; e < 4; e++) {
            int r = max(-127, min(127, __float2int_rn(v[e] * QS)));
            pk |= ((u32)(r & 255)) << (8 * e);
        }
        w[j] = pk;
    }
    uint4* dst = (uint4*)(g_q8 + (size_t)p * 64);
    dst[0] = make_uint4(w[0], w[1], w[2], w[3]);
    dst[1] = make_uint4(w[4], w[5], w[6], w[7]);
    dst[2] = make_uint4(w[8], w[9], w[10], w[11]);
    dst[3] = make_uint4(w[12], w[13], w[14], w[15]);
}

// ---------------------------------------------------------------------------
// tau_kernel: per-query threshold from 2048-row sample; resets counter
// ---------------------------------------------------------------------------
__global__ void __launch_bounds__(256)
tau_kernel() {
    __shared__ int s_s[NSMP];
    __shared__ int rv[8], rp[8];
    __shared__ int s_tau;

    const int q = blockIdx.x, tid = threadIdx.x;
    const int w = tid >> 5, lane = tid & 31;

    u32 qw[16];
    load16(g_q8 + (size_t)q * 64, qw);

#pragma unroll
    for (int i = 0; i < NSMP / 256; i++) {
        const int j = tid + i * 256;
        const int r = j * SSTRIDE;
        u32 tw[16];
        load16(g_t8 + (size_t)r * 64, tw);
        int d = 0;
#pragma unroll
        for (int k = 0; k < 16; k++) d = __dp4a((int)tw[k], (int)qw[k], d);
        s_s[j] = g_nint[r] - 2 * d;
    }
    __syncthreads();

    for (int k = 0; k < NTAU; k++) {
        int v = 0x7FFFFFFF, p = 0;
        for (int i = tid; i < NSMP; i += 256)
            if (s_s[i] < v) { v = s_s[i]; p = i; }
#pragma unroll
        for (int o = 16; o > 0; o >>= 1) {
            int ov = __shfl_down_sync(0xffffffffu, v, o);
            int op = __shfl_down_sync(0xffffffffu, p, o);
            if (ov < v) { v = ov; p = op; }
        }
        if (lane == 0) { rv[w] = v; rp[w] = p; }
        __syncthreads();
        if (tid == 0) {
            int bv = rv[0], bp = rp[0];
#pragma unroll
            for (int x = 1; x < 8; x++)
                if (rv[x] < bv) { bv = rv[x]; bp = rp[x]; }
            s_s[bp] = 0x7FFFFFFF;
            if (k == NTAU - 1) s_tau = bv;
        }
        __syncthreads();
    }
    if (tid == 0) { g_tau[q] = s_tau; g_cnt[q] = 0u; }
}

// ---------------------------------------------------------------------------
// sweep: full dp4a sweep (round-15 body) + score stored with each qualifier
// 296 CTAs x 512 threads (2/SM), 2 queries/thread
// ---------------------------------------------------------------------------
__global__ void __launch_bounds__(512, 2)
sweep_kernel() {
    __shared__ __align__(16) u32 s_t[3][TILE * 16];   // 3 x 4KB tile
    __shared__ __align__(16) int s_n[3][TILE];        // 3 x 256B norms

    const int tid = threadIdx.x;
    const int range = blockIdx.x;
    const int q0 = tid * 2, q1 = q0 + 1;
    const u32 sbt = smem_u32(&s_t[0][0]);
    const u32 sbn = smem_u32(&s_n[0][0]);

    u32 q0w[16], q1w[16];
    load16(g_q8 + (size_t)q0 * 64, q0w);
    load16(g_q8 + (size_t)q1 * 64, q1w);
    const int t0 = g_tau[q0] + 1;     // qualify: s < t0
    const int t1 = g_tau[q1] + 1;

    const size_t rbase = (size_t)range * RC;
    auto prefetch = [&](int t, int st) {
        const unsigned char* src = g_t8 + (rbase + (size_t)t * TILE) * 64;
        if (tid < 256) cpa16(sbt + st * 4096 + tid * 16, src + tid * 16);
        else if (tid < 272)
            cpa16(sbn + st * 256 + (tid - 256) * 16,
                  (const unsigned char*)(g_nint + rbase + (size_t)t * TILE) + (tid - 256) * 16);
        cpa_commit();
    };

    prefetch(0, 0); prefetch(1, 1); prefetch(2, 2);

    for (int t = 0; t < TPT; t++) {
        const int st = t % 3;
        cpa_wait2();
        __syncthreads();

        const u32* tp = s_t[st];
        const int* np = s_n[st];
        const int pbase = range * RC + t * TILE;

#pragma unroll 4
        for (int c = 0; c < TILE; c++) {
            u32 X[16];
            load16((const unsigned char*)(tp + c * 16), X);
            const int n = np[c];

            int a0a = 0, a0b = 0, a1a = 0, a1b = 0;   // 4 independent chains
#pragma unroll
            for (int j = 0; j < 8; j++) {
                a0a = __dp4a((int)X[j],     (int)q0w[j],     a0a);
                a1a = __dp4a((int)X[j],     (int)q1w[j],     a1a);
                a0b = __dp4a((int)X[j + 8], (int)q0w[j + 8], a0b);
                a1b = __dp4a((int)X[j + 8], (int)q1w[j + 8], a1b);
            }
            const int s0 = n - 2 * (a0a + a0b);
            const int s1 = n - 2 * (a1a + a1b);

            if (min(s0 - t0, s1 - t1) < 0) {
                const int p0 = pbase + c;
                if (s0 < t0) {
                    u32 i = atomicAdd(&g_cnt[q0], 1u);
                    if (i < CAP) {
                        g_cand[(size_t)q0 * CAP + i] = p0;
                        g_csc[(size_t)q0 * CAP + i] = s0;
                    }
                }
                if (s1 < t1) {
                    u32 i = atomicAdd(&g_cnt[q1], 1u);
                    if (i < CAP) {
                        g_cand[(size_t)q1 * CAP + i] = p0;
                        g_csc[(size_t)q1 * CAP + i] = s1;
                    }
                }
            }
        }

        __syncthreads();
        if (t + 3 < TPT) prefetch(t + 3, st);
        else cpa_commit();
    }
}

// ---------------------------------------------------------------------------
// merge v2: binary-search quant-top-~80 -> exact fp32 rerank (<=128 rows)
// -> O(m^2) rank-by-counting -> deterministic weighted sum
// ---------------------------------------------------------------------------
__global__ void __launch_bounds__(512)
merge_kernel(const float* __restrict__ keys, const float* __restrict__ tkeys,
             const float* __restrict__ tvals, float* __restrict__ out) {
    __shared__ int s_sc[CAP];                 // 24KB quant scores
    __shared__ __align__(16) float qs[ND];
    __shared__ int s_cnt;
    __shared__ int s_m;
    __shared__ int s_selidx[MCAP];
    __shared__ int s_row[MCAP];
    __shared__ float s_d[MCAP];
    __shared__ float ws[NK], wv[NK];

    const int q = blockIdx.x, tid = threadIdx.x;
    const int w = tid >> 5, lane = tid & 31;
    const int n = min((int)g_cnt[q], CAP);
    const int* cand = g_cand + (size_t)q * CAP;
    const int* csc = g_csc + (size_t)q * CAP;

    for (int i = tid; i < n; i += 512) s_sc[i] = csc[i];
    if (tid < ND) qs[tid] = keys[(size_t)q * ND + tid];
    if (tid < NK) { ws[tid] = 0.f; wv[tid] = 0.f; }
    __syncthreads();

    // --- binary search smallest T with count(s < T) >= MQ ---
    int T = g_tau[q] + 1;                     // all qualifiers are < this
    if (n > MQ) {
        int lo = -(1 << 19), hi = T;          // cnt(<lo)=0 < MQ <= cnt(<hi)=n
        while (hi - lo > 1) {
            const int mid = (int)(((long long)lo + hi) >> 1);
            if (tid == 0) s_cnt = 0;
            __syncthreads();
            int c = 0;
            for (int i = tid; i < n; i += 512) c += (s_sc[i] < mid);
#pragma unroll
            for (int o = 16; o > 0; o >>= 1)
                c += __shfl_down_sync(0xffffffffu, c, o);
            if (lane == 0) atomicAdd(&s_cnt, c);
            __syncthreads();
            const int tot = s_cnt;
            __syncthreads();
            if (tot >= MQ) hi = mid; else lo = mid;
        }
        T = hi;
    }

    // --- collect candidates with s < T (approx MQ, cap MCAP) ---
    if (tid == 0) s_m = 0;
    __syncthreads();
    for (int i = tid; i < n; i += 512) {
        if (s_sc[i] < T) {
            int slot = atomicAdd(&s_m, 1);
            if (slot < MCAP) s_selidx[slot] = i;
        }
    }
    __syncthreads();
    const int m = min(s_m, MCAP);
    if (tid < m) s_row[tid] = cand[s_selidx[tid]];
    __syncthreads();

    // --- exact fp32 distances: warp per row, 2 rows in flight, 16 warps ---
    {
        const float2 qv = ((const float2*)qs)[lane];
        for (int cb = w; cb < m; cb += 32) {
            const int cb2 = cb + 16;
            const bool has2 = cb2 < m;
            const int ra = s_row[cb];
            const int rb = s_row[has2 ? cb2 : cb];
            const float2 ta = ((const float2*)(tkeys + (size_t)ra * ND))[lane];
            const float2 tb = ((const float2*)(tkeys + (size_t)rb * ND))[lane];
            float a0 = qv.x - ta.x, a1 = qv.y - ta.y;
            float b0 = qv.x - tb.x, b1 = qv.y - tb.y;
            float sa = fmaf(a0, a0, a1 * a1);
            float sc = fmaf(b0, b0, b1 * b1);
#pragma unroll
            for (int o = 16; o > 0; o >>= 1) {
                sa += __shfl_xor_sync(0xffffffffu, sa, o);
                sc += __shfl_xor_sync(0xffffffffu, sc, o);
            }
            if (lane == 0) {
                s_d[cb] = sa;
                if (has2) s_d[cb2] = sc;
            }
        }
    }
    __syncthreads();

    // --- rank by counting; top-50 contribute at ws[rank] (deterministic) ---
    if (tid < m) {
        const float di = s_d[tid];
        int rank = 0;
        for (int j = 0; j < m; j++) {
            const float dj = s_d[j];
            rank += (dj < di) || (dj == di && j < tid);
        }
        if (rank < NK) {
            const float wgt = 1.0f / (di + 1e-3f);
            ws[rank] = wgt;
            wv[rank] = wgt * tvals[s_row[tid]];
        }
    }
    __syncthreads();
    if (tid == 0) {
        float sw = 0.f, sv = 0.f;
#pragma unroll
        for (int k = 0; k < NK; k++) { sw += ws[k]; sv += wv[k]; }
        out[q] = sv / sw;
    }
}

// ---------------------------------------------------------------------------
extern "C" void kernel_launch(void* const* d_in, const int* in_sizes, int n_in,
                              void* d_out, int out_size) {
    const float* keys  = (const float*)d_in[0];   // [1024, 64]
    const float* tkeys = (const float*)d_in[1];   // [500000, 64]
    const float* tvals = (const float*)d_in[2];   // [500000]
    float* out = (float*)d_out;                   // [1024]

    prep_t<<<NPAD / 16, 256>>>(tkeys);            // 31968 blocks, exact cover
    prep_q<<<4, 256>>>(keys);
    tau_kernel<<<NB, 256>>>();                    // thresholds + counter reset
    sweep_kernel<<<NR, 512>>>();
    merge_kernel<<<NB, 512>>>(keys, tkeys, tvals, out);
}